// round 15
// baseline (speedup 1.0000x reference)
#include <cuda_runtime.h>
#include <cuda_fp16.h>
#include <cstdint>

#define C 32
#define H 128
#define W 256
#define YS2 19       // y_sh row stride in u32 (half2): gcd(19,32)=1 -> conflict-free LDS.32
#define YROWS 257    // rows 0..255 = y columns; row 256 = zero row (both boundaries)
#define GO 66
#define GS 67        // gather: lane w-stride 1 -> bank stride 3 -> conflict-free
#define GROWS 257    // rows 0..255 real; row 256 pads the w=255 b-store
#define NT 256

typedef unsigned long long u64;

__device__ __forceinline__ u64 pack2(float lo, float hi) {
    u64 r; asm("mov.b64 %0, {%1, %2};" : "=l"(r) : "f"(lo), "f"(hi)); return r;
}
__device__ __forceinline__ void ffma2(u64& acc, u64 a, u64 b) {
    asm("fma.rn.f32x2 %0, %1, %2, %0;" : "+l"(acc) : "l"(a), "l"(b));
}
__device__ __forceinline__ u64 add2(u64 a, u64 b) {
    u64 r; asm("add.rn.f32x2 %0, %1, %2;" : "=l"(r) : "l"(a), "l"(b)); return r;
}
__device__ __forceinline__ float hadd2(u64 v) {
    float lo, hi; asm("mov.b64 {%0, %1}, %2;" : "=f"(lo), "=f"(hi) : "l"(v)); return lo + hi;
}
// half2 (lo,hi) -> f32x2 u64 operand {lo,hi}
__device__ __forceinline__ u64 h2f2(uint32_t h) {
    u64 r;
    asm("{\n\t.reg .b16 l, h;\n\t.reg .f32 f0, f1;\n\t"
        "mov.b32 {l, h}, %1;\n\t"
        "cvt.f32.f16 f0, l;\n\tcvt.f32.f16 f1, h;\n\t"
        "mov.b64 %0, {f0, f1};\n\t}" : "=l"(r) : "r"(h));
    return r;
}
// pack two f32 -> half2 {lo=v0, hi=v1}
__device__ __forceinline__ uint32_t f2h2(float v0, float v1) {
    uint32_t r;
    asm("cvt.rn.f16x2.f32 %0, %1, %2;" : "=r"(r) : "f"(v1), "f"(v0));
    return r;
}

__global__ __launch_bounds__(NT, 2)
void cost_volume_kernel(const float* __restrict__ x, const float* __restrict__ y,
                        const float* __restrict__ disp, float* __restrict__ out,
                        int D) {
    extern __shared__ float sm[];
    uint32_t* y_sh = (uint32_t*)sm;            // YROWS * YS2 u32 (half2 [col][c/2])
    float* G_sh = sm + YROWS * YS2;            // GROWS * GS banded Gram (f32)

    const int bh = blockIdx.x;
    const int b = bh / H;
    const int h = bh - b * H;
    const int tid = threadIdx.x;
    const size_t HW = (size_t)H * W;
    const float* ybase = y + ((size_t)b * C * H + h) * W;
    const float* xbase = x + ((size_t)b * C * H + h) * W;

    // ---- Phase 1: stage y row transposed as half2 (row r = y column r).
    // Row 256 is the zero row implementing the reference's zero-padding mask.
    {
        const float* src = ybase + tid;
        uint32_t* dst = y_sh + tid * YS2;
        #pragma unroll
        for (int k = 0; k < 16; k++) {
            float v0 = src[(size_t)(2 * k) * HW];
            float v1 = src[(size_t)(2 * k + 1) * HW];
            dst[k] = f2h2(v0, v1);               // conflict-free STS.32 (stride 19)
        }
    }
    if (tid < YS2) y_sh[256 * YS2 + tid] = 0u;   // half2 zeros

    // x columns w and w+1, all 32 channels fp32, packed for FFMA2.
    const int w = tid;                // blockDim.x == W
    const bool has_b = (w + 1 < W);
    u64 xa[16], xb[16];
    #pragma unroll
    for (int k = 0; k < 16; k++) {
        float a0 = xbase[(size_t)(2 * k) * HW + w];
        float a1 = xbase[(size_t)(2 * k + 1) * HW + w];
        xa[k] = pack2(a0, a1);
        float b0 = has_b ? xbase[(size_t)(2 * k) * HW + w + 1] : 0.f;
        float b1 = has_b ? xbase[(size_t)(2 * k + 1) * HW + w + 1] : 0.f;
        xb[k] = pack2(b0, b1);
    }
    __syncthreads();

    // ---- Phase 2: banded Gram  G[w][o] = sum_c x[c][w] * y[c][w+o-64]
    // Anti-diagonal pairing: (w, o0) and (w+1, o0-1) share y column w+o0-64.
    // y read as 16 conflict-free LDS.32 (half crossbar bytes of the fp32
    // version); converted to f32 pairs at consume time (x and G stay fp32).
    float* ga = G_sh + w * GS;
    float* gb = G_sh + (w + 1) * GS;
    #pragma unroll 1
    for (int o0 = 1; o0 <= 65; o0 += 2) {
        int r = w + o0 - 64;
        if ((unsigned)r > 255u) r = 256;          // both boundaries -> zero row
        const uint32_t* yp = y_sh + r * YS2;
        uint32_t hbuf[16];
        #pragma unroll
        for (int k = 0; k < 16; k++) hbuf[k] = yp[k];   // MLP-16 scalar loads
        u64 a0 = 0, a1 = 0, a2 = 0, a3 = 0;
        u64 b0 = 0, b1 = 0, b2 = 0, b3 = 0;
        #pragma unroll
        for (int k = 0; k < 16; k += 4) {
            u64 y0 = h2f2(hbuf[k + 0]);
            u64 y1 = h2f2(hbuf[k + 1]);
            u64 y2 = h2f2(hbuf[k + 2]);
            u64 y3 = h2f2(hbuf[k + 3]);
            ffma2(a0, xa[k + 0], y0);  ffma2(b0, xb[k + 0], y0);
            ffma2(a1, xa[k + 1], y1);  ffma2(b1, xb[k + 1], y1);
            ffma2(a2, xa[k + 2], y2);  ffma2(b2, xb[k + 2], y2);
            ffma2(a3, xa[k + 3], y3);  ffma2(b3, xb[k + 3], y3);
        }
        ga[o0]     = hadd2(add2(add2(a0, a1), add2(a2, a3)));
        gb[o0 - 1] = hadd2(add2(add2(b0, b1), add2(b2, b3)));
    }
    // Cleanup: entries (w=0, even o): zero except the single real dot at o=64.
    if (tid < 33) {
        int o = 2 * tid;
        float s = 0.f;
        if (o == 64) {
            u64 acc = 0;
            #pragma unroll
            for (int k = 0; k < 16; k++) {
                u64 yv = h2f2(y_sh[k]);           // row 0 = y column 0
                u64 xv = pack2(xbase[(size_t)(2 * k) * HW],
                               xbase[(size_t)(2 * k + 1) * HW]);
                ffma2(acc, xv, yv);
            }
            s = hadd2(acc);
        }
        G_sh[o] = s;
    }

    // ---- Phase 3: strided-w ownership (R14). Thread (q, g) owns w in
    // {q, q+64, q+128, q+192}, d in [12g, 12g+12): conflict-free gather LDS
    // (bank stride 3) + coalesced scalar LDG/STG.
    const float* dbase = disp + ((size_t)b * D * H + h) * W;
    float* obase = out + ((size_t)b * D * H + h) * W;

    // disp in [0,64) => o in [0,64], o+1 in [1,65]: always in-band, no guards.
    if (D == 48) {
        const int q = tid & 63;
        const int d0 = (tid >> 6) * 12;
        float dv[12];
        #pragma unroll
        for (int j = 0; j < 12; j++)                   // slot 0 prefetch, issued
            dv[j] = dbase[(size_t)(d0 + j) * HW + q];  // BEFORE the barrier
        __syncthreads();
        #pragma unroll
        for (int s = 0; s < 4; s++) {
            const int w3 = q + s * 64;
            float dnx[12];
            if (s < 3) {
                #pragma unroll
                for (int j = 0; j < 12; j++)
                    dnx[j] = dbase[(size_t)(d0 + j) * HW + w3 + 64];
            }
            const float* gr = G_sh + w3 * GS;
            const float wf = (float)w3;
            #pragma unroll
            for (int j = 0; j < 12; j++) {
                float px = wf - dv[j];
                float x0f = floorf(px);
                float fx = px - x0f;
                int o = (int)x0f - w3 + 64;
                float g0 = gr[o];
                float g1 = gr[o + 1];
                obase[(size_t)(d0 + j) * HW + w3] = (g0 + (g1 - g0) * fx) * (1.0f / C);
            }
            if (s < 3) {
                #pragma unroll
                for (int j = 0; j < 12; j++) dv[j] = dnx[j];
            }
        }
    } else {
        __syncthreads();
        const int total4 = D * (W / 4);
        #pragma unroll 4
        for (int i = tid; i < total4; i += NT) {
            int d = i >> 6;
            int w4 = (i & 63) << 2;
            float4 dvv = *(const float4*)(dbase + (size_t)d * HW + w4);
            float4 res;
            #pragma unroll
            for (int j = 0; j < 4; j++) {
                int ww = w4 + j;
                float px = (float)ww - (&dvv.x)[j];
                float x0f = floorf(px);
                float fx = px - x0f;
                int o = (int)x0f - ww + 64;
                float g0 = ((unsigned)o < GO) ? G_sh[ww * GS + o] : 0.f;
                float g1 = ((unsigned)(o + 1) < GO) ? G_sh[ww * GS + o + 1] : 0.f;
                (&res.x)[j] = (g0 + (g1 - g0) * fx) * (1.0f / C);
            }
            *(float4*)(obase + (size_t)d * HW + w4) = res;
        }
    }
}

extern "C" void kernel_launch(void* const* d_in, const int* in_sizes, int n_in,
                              void* d_out, int out_size) {
    const float* x = (const float*)d_in[0];
    const float* y = (const float*)d_in[1];
    const float* disp = (const float*)d_in[2];
    int B = in_sizes[0] / (C * H * W);
    int D = in_sizes[2] / (B * H * W);
    int smem = (YROWS * YS2 + GROWS * GS) * (int)sizeof(float);
    cudaFuncSetAttribute(cost_volume_kernel,
                         cudaFuncAttributeMaxDynamicSharedMemorySize, smem);
    cost_volume_kernel<<<B * H, NT, smem>>>(x, y, disp, (float*)d_out, D);
}

// round 16
// speedup vs baseline: 1.3907x; 1.3907x over previous
#include <cuda_runtime.h>
#include <cuda_fp16.h>
#include <cstdint>

#define C 32
#define H 128
#define W 256
#define XS 20        // x_sh row stride in u32 (80B): frag-load bank 20g+t4 -> conflict-free
#define YSY 20       // y_sh row stride in u32
#define YR 328       // sj = jj + 64 in [0, 328); zeros outside sj in [64, 320)
#define GO 66
#define GS 67        // gather: lane w-stride 1 -> bank stride 3 -> conflict-free
#define NT 256

// pack two f32 -> half2 {lo=v0, hi=v1}
__device__ __forceinline__ uint32_t f2h2(float v0, float v1) {
    uint32_t r;
    asm("cvt.rn.f16x2.f32 %0, %1, %2;" : "=r"(r) : "f"(v1), "f"(v0));
    return r;
}

__global__ __launch_bounds__(NT, 2)
void cost_volume_kernel(const float* __restrict__ x, const float* __restrict__ y,
                        const float* __restrict__ disp, float* __restrict__ out,
                        int D) {
    extern __shared__ uint32_t smu[];
    uint32_t* x_sh = smu;                        // [256][XS] halves [w][c]
    uint32_t* y_sh = smu + 256 * XS;             // [YR][YSY] halves [sj][c]
    float* G_sh = (float*)(smu + 256 * XS + YR * YSY);  // [256][GS] fp32 band

    const int bh = blockIdx.x;
    const int b = bh / H;
    const int h = bh - b * H;
    const int tid = threadIdx.x;
    const size_t HW = (size_t)H * W;
    const float* ybase = y + ((size_t)b * C * H + h) * W;
    const float* xbase = x + ((size_t)b * C * H + h) * W;

    // ---- Phase 1: stage x and y rows transposed to fp16 pairs.
    {   // x: thread tid = column w
        const float* src = xbase + tid;
        uint32_t* dst = x_sh + tid * XS;
        #pragma unroll
        for (int k = 0; k < 16; k++)
            dst[k] = f2h2(src[(size_t)(2 * k) * HW], src[(size_t)(2 * k + 1) * HW]);
    }
    {   // y: thread tid = column j -> row sj = j + 64
        const float* src = ybase + tid;
        uint32_t* dst = y_sh + (tid + 64) * YSY;
        #pragma unroll
        for (int k = 0; k < 16; k++)
            dst[k] = f2h2(src[(size_t)(2 * k) * HW], src[(size_t)(2 * k + 1) * HW]);
    }
    // zero rows: sj in [0,64) and [320,328)  (reference's zero-padding mask)
    for (int i = tid; i < 72 * 16; i += NT) {
        int r = i >> 4;
        int k = i & 15;
        int sj = (r < 64) ? r : (r + 256);
        y_sh[sj * YSY + k] = 0u;
    }

    // Phase-3 disp prefetch (R14 strided-w scheme), issued before the barrier.
    const float* dbase = disp + ((size_t)b * D * H + h) * W;
    float* obase = out + ((size_t)b * D * H + h) * W;
    const int q = tid & 63;
    const int d0 = (tid >> 6) * 12;
    float dv[12];
    const bool fast = (D == 48);
    if (fast) {
        #pragma unroll
        for (int j = 0; j < 12; j++)
            dv[j] = dbase[(size_t)(d0 + j) * HW + q];
    }
    __syncthreads();

    // ---- Phase 2: banded Gram via mma.sync m16n8k16 (f16 x f16 -> f32).
    // P[w][jj] = sum_c x[c][w] * y[c][jj];  G[w][o] = P[w][w + o - 64].
    // Each warp: 2 M-tiles x 11 N-tiles; jj window [w0-64, w0+24) covers the
    // whole band of the tile -> full coverage, no cleanup.
    {
        const int lane = tid & 31;
        const int g = lane >> 2;          // group row 0..7
        const int t4 = lane & 3;          // thread-in-group
        const int wid = tid >> 5;
        #pragma unroll
        for (int mi = 0; mi < 2; mi++) {
            const int mt = wid + mi * 8;      // M-tile 0..15
            const int w0 = mt << 4;
            const uint32_t* xr0 = x_sh + (w0 + g) * XS;
            const uint32_t* xr8 = x_sh + (w0 + g + 8) * XS;
            // A fragments, both k-steps (k cols: u32 idx t4, t4+4 | t4+8, t4+12)
            uint32_t a00 = xr0[t4],     a01 = xr8[t4];
            uint32_t a02 = xr0[t4 + 4], a03 = xr8[t4 + 4];
            uint32_t a10 = xr0[t4 + 8], a11 = xr8[t4 + 8];
            uint32_t a12 = xr0[t4 + 12], a13 = xr8[t4 + 12];
            float* grow = G_sh + (w0 + g) * GS;
            float* grow8 = G_sh + (w0 + g + 8) * GS;
            #pragma unroll
            for (int nt = 0; nt < 11; nt++) {
                const uint32_t* yr = y_sh + (w0 + nt * 8 + g) * YSY;  // sj of n-col g
                uint32_t b00 = yr[t4];      // k = 2t4, 2t4+1
                uint32_t b01 = yr[t4 + 4];  // k = 2t4+8
                uint32_t b10 = yr[t4 + 8];  // kstep1
                uint32_t b11 = yr[t4 + 12];
                float c0 = 0.f, c1 = 0.f, c2 = 0.f, c3 = 0.f;
                asm volatile(
                    "mma.sync.aligned.m16n8k16.row.col.f32.f16.f16.f32 "
                    "{%0,%1,%2,%3}, {%4,%5,%6,%7}, {%8,%9}, {%0,%1,%2,%3};"
                    : "+f"(c0), "+f"(c1), "+f"(c2), "+f"(c3)
                    : "r"(a00), "r"(a01), "r"(a02), "r"(a03), "r"(b00), "r"(b01));
                asm volatile(
                    "mma.sync.aligned.m16n8k16.row.col.f32.f16.f16.f32 "
                    "{%0,%1,%2,%3}, {%4,%5,%6,%7}, {%8,%9}, {%0,%1,%2,%3};"
                    : "+f"(c0), "+f"(c1), "+f"(c2), "+f"(c3)
                    : "r"(a10), "r"(a11), "r"(a12), "r"(a13), "r"(b10), "r"(b11));
                // D(row, col): rows g (c0,c1), g+8 (c2,c3); cols 2t4, 2t4+1.
                // o = 8*nt + col - row
                int o0 = nt * 8 + 2 * t4 - g;
                if ((unsigned)o0 <= 65u) grow[o0] = c0;
                if ((unsigned)(o0 + 1) <= 65u) grow[o0 + 1] = c1;
                int o8 = o0 - 8;
                if ((unsigned)o8 <= 65u) grow8[o8] = c2;
                if ((unsigned)(o8 + 1) <= 65u) grow8[o8 + 1] = c3;
            }
        }
    }
    __syncthreads();

    // ---- Phase 3: strided-w gather (R14). disp in [0,64) => o in [0,64],
    // o+1 in [1,65]: always in-band -> no guards on the fast path.
    if (fast) {
        #pragma unroll
        for (int s = 0; s < 4; s++) {
            const int w3 = q + s * 64;
            float dnx[12];
            if (s < 3) {
                #pragma unroll
                for (int j = 0; j < 12; j++)
                    dnx[j] = dbase[(size_t)(d0 + j) * HW + w3 + 64];
            }
            const float* gr = G_sh + w3 * GS;
            const float wf = (float)w3;
            #pragma unroll
            for (int j = 0; j < 12; j++) {
                float px = wf - dv[j];
                float x0f = floorf(px);
                float fx = px - x0f;
                int o = (int)x0f - w3 + 64;
                float g0 = gr[o];
                float g1 = gr[o + 1];
                obase[(size_t)(d0 + j) * HW + w3] = (g0 + (g1 - g0) * fx) * (1.0f / C);
            }
            if (s < 3) {
                #pragma unroll
                for (int j = 0; j < 12; j++) dv[j] = dnx[j];
            }
        }
    } else {
        const int total4 = D * (W / 4);
        #pragma unroll 4
        for (int i = tid; i < total4; i += NT) {
            int d = i >> 6;
            int w4 = (i & 63) << 2;
            float4 dvv = *(const float4*)(dbase + (size_t)d * HW + w4);
            float4 res;
            #pragma unroll
            for (int j = 0; j < 4; j++) {
                int ww = w4 + j;
                float px = (float)ww - (&dvv.x)[j];
                float x0f = floorf(px);
                float fx = px - x0f;
                int o = (int)x0f - ww + 64;
                float g0 = ((unsigned)o < GO) ? G_sh[ww * GS + o] : 0.f;
                float g1 = ((unsigned)(o + 1) < GO) ? G_sh[ww * GS + o + 1] : 0.f;
                (&res.x)[j] = (g0 + (g1 - g0) * fx) * (1.0f / C);
            }
            *(float4*)(obase + (size_t)d * HW + w4) = res;
        }
    }
}

extern "C" void kernel_launch(void* const* d_in, const int* in_sizes, int n_in,
                              void* d_out, int out_size) {
    const float* x = (const float*)d_in[0];
    const float* y = (const float*)d_in[1];
    const float* disp = (const float*)d_in[2];
    int B = in_sizes[0] / (C * H * W);
    int D = in_sizes[2] / (B * H * W);
    int smem = (256 * XS + YR * YSY + 256 * GS) * 4;
    cudaFuncSetAttribute(cost_volume_kernel,
                         cudaFuncAttributeMaxDynamicSharedMemorySize, smem);
    cost_volume_kernel<<<B * H, NT, smem>>>(x, y, disp, (float*)d_out, D);
}